// round 7
// baseline (speedup 1.0000x reference)
#include <cuda_runtime.h>
#include <cstdint>

#define T_STEPS 128
#define B_TOT   8192
#define H_DIM   256
#define BETA    0.9f
#define NDIR    16
#define SLACK   1.0205f   // sec(pi/16)=1.01959 + fp margin; strictly conservative

typedef unsigned long long u64;

// --- static device scratch (no allocation allowed) ---
__device__ float         d_D[B_TOT * NDIR];      // directional support maxima, >= 0
__device__ int           d_cnt[B_TOT];           // survivors per batch
__device__ unsigned char d_list[B_TOT][H_DIM];   // survivor h indices per batch

__device__ const float c_cs[NDIR] = {
     1.0f,  0.92387953f,  0.70710678f,  0.38268343f,
     0.0f, -0.38268343f, -0.70710678f, -0.92387953f,
    -1.0f, -0.92387953f, -0.70710678f, -0.38268343f,
     0.0f,  0.38268343f,  0.70710678f,  0.92387953f };
__device__ const float c_sn[NDIR] = {
     0.0f,  0.38268343f,  0.70710678f,  0.92387953f,
     1.0f,  0.92387953f,  0.70710678f,  0.38268343f,
     0.0f, -0.38268343f, -0.70710678f, -0.92387953f,
    -1.0f, -0.92387953f, -0.70710678f, -0.38268343f };

// ---- packed f32x2 helpers ----
__device__ __forceinline__ u64 pk2(float lo, float hi) {
    u64 r; asm("mov.b64 %0, {%1, %2};" : "=l"(r) : "f"(lo), "f"(hi)); return r;
}
__device__ __forceinline__ void unpk2(u64 v, float& lo, float& hi) {
    asm("mov.b64 {%0, %1}, %2;" : "=f"(lo), "=f"(hi) : "l"(v));
}
__device__ __forceinline__ u64 fma2(u64 a, u64 b, u64 c) {
    u64 d; asm("fma.rn.f32x2 %0, %1, %2, %3;" : "=l"(d) : "l"(a), "l"(b), "l"(c)); return d;
}
__device__ __forceinline__ u64 mul2(u64 a, u64 b) {
    u64 d; asm("mul.rn.f32x2 %0, %1, %2;" : "=l"(d) : "l"(a), "l"(b)); return d;
}
__device__ __forceinline__ u64 add2(u64 a, u64 b) {
    u64 d; asm("add.rn.f32x2 %0, %1, %2;" : "=l"(d) : "l"(a), "l"(b)); return d;
}
__device__ __forceinline__ u64 gt1_2(u64 m) {
    u64 r;
    asm("{\n\t"
        ".reg .f32 plo, phi, rl, rh;\n\t"
        "mov.b64 {plo, phi}, %1;\n\t"
        "set.gt.f32.f32 rl, plo, 0f3F800000;\n\t"
        "set.gt.f32.f32 rh, phi, 0f3F800000;\n\t"
        "mov.b64 %0, {rl, rh};\n\t"
        "}" : "=l"(r) : "l"(m));
    return r;
}

// K1: per (b, dir): v_t = beta*v + x_t ;  D = max_t max(0, u_k . v_t)
// 16 consecutive threads share b -> x load is a warp broadcast (2 addrs/warp).
__global__ void __launch_bounds__(256) k1_dirmax(const float2* __restrict__ x2) {
    int idx = blockIdx.x * 256 + threadIdx.x;   // = b*16 + k
    int k = idx & 15;
    int b = idx >> 4;
    float cs = c_cs[k], sn = c_sn[k];
    float A = 0.f, B = 0.f, D = 0.f;            // D init 0 == clamp to 0
    #pragma unroll 4
    for (int t = 0; t < T_STEPS; ++t) {
        float2 xv = __ldg(&x2[(size_t)t * B_TOT + b]);
        A = fmaf(A, BETA, xv.x);
        B = fmaf(B, BETA, xv.y);
        D = fmaxf(D, fmaf(A, cs, B * sn));
    }
    d_D[idx] = D;
}

// K2: per (b,h) conservative never-spikes test + deterministic ballot compaction.
// Also zeroes out[b][*] (replaces the old k0 launch).
__global__ void __launch_bounds__(256) k2_filter(const float2* __restrict__ w1p,
                                                 float* __restrict__ out) {
    const int b = blockIdx.x;
    const int h = threadIdx.x;
    __shared__ float sD[NDIR];
    __shared__ int wcnt[8], wbase[8];
    if (h < NDIR) sD[h] = d_D[b * NDIR + h];
    if (h < 2)    out[b * 2 + h] = 0.f;
    __syncthreads();

    float2 w = w1p[h];
    float R  = sqrtf(fmaf(w.x, w.x, w.y * w.y));
    float th = atan2f(w.y, w.x);                       // sector of w
    int k = ((int)floorf(th * 2.5464790894703255f) + 32) & 15;   // 8/pi
    float mD = fmaxf(sD[k], fmaxf(sD[(k + 1) & 15], sD[(k + 15) & 15]));
    bool pred = (R * mD * SLACK >= 1.0f);              // may spike -> survivor

    unsigned mask = __ballot_sync(0xffffffffu, pred);
    int wrp = h >> 5, lane = h & 31;
    if (lane == 0) wcnt[wrp] = __popc(mask);
    __syncthreads();
    if (h == 0) {
        int s = 0;
        #pragma unroll
        for (int i = 0; i < 8; ++i) { wbase[i] = s; s += wcnt[i]; }
        d_cnt[b] = s;
    }
    __syncthreads();
    if (pred) {
        int pos = wbase[wrp] + __popc(mask & ((1u << lane) - 1u));
        d_list[b][pos] = (unsigned char)h;
    }
}

// K3: exact reference-ordered LIF scan for survivors only.
// One warp per batch; each lane handles TWO survivors packed in f32x2
// (one pass covers 64 survivors). x staged in smem pre-duplicated
// {x0,x0,x1,x1} so one broadcast LDS.128 feeds both packed operands.
__global__ void __launch_bounds__(256) k3_scan(const float2* __restrict__ x2,
                                               const float2* __restrict__ w1p,
                                               const float*  __restrict__ w2,
                                               float* __restrict__ out) {
    const int wrp = threadIdx.x >> 5, lane = threadIdx.x & 31;
    const int b = blockIdx.x * 8 + wrp;
    const int n = d_cnt[b];
    if (n == 0) return;                              // warp-uniform; out already 0

    __shared__ __align__(16) float4 sx[8][T_STEPS];  // 16KB
    for (int t = lane; t < T_STEPS; t += 32) {
        float2 xv = x2[(size_t)t * B_TOT + b];
        sx[wrp][t] = make_float4(xv.x, xv.x, xv.y, xv.y);
    }
    __syncwarp();
    const ulonglong2* __restrict__ xs = (const ulonglong2*)&sx[wrp][0];

    const u64 BETA2 = 0x3F6666663F666666ULL;  // (0.9f, 0.9f)
    const u64 NEG12 = 0xBF800000BF800000ULL;  // (-1.0f, -1.0f)

    float a0 = 0.f, a1 = 0.f;
    for (int base = 0; base < n; base += 64) {
        const int ia = base + lane, ib = base + 32 + lane;
        const bool acta = ia < n, actb = ib < n;
        const int ha = acta ? (int)d_list[b][ia] : 0;
        const int hb = actb ? (int)d_list[b][ib] : 0;
        const float2 wa = w1p[ha], wb = w1p[hb];
        const u64 w0p = pk2(wa.x, wb.x);
        const u64 w1p_ = pk2(wa.y, wb.y);

        u64 m = 0, cnt = 0;
        #pragma unroll 4
        for (int t = 0; t < 118; ++t) {
            ulonglong2 q = xs[t];                  // q.x=(x0,x0) q.y=(x1,x1)
            u64 s = gt1_2(m);                      // reset from prev mem
            m = fma2(m, BETA2, fma2(q.x, w0p, mul2(q.y, w1p_)));
            m = fma2(s, NEG12, m);
        }
        #pragma unroll
        for (int t = 118; t < T_STEPS; ++t) {
            ulonglong2 q = xs[t];
            u64 s = gt1_2(m);
            m = fma2(m, BETA2, fma2(q.x, w0p, mul2(q.y, w1p_)));
            m = fma2(s, NEG12, m);
            cnt = add2(cnt, gt1_2(m));             // spk_t, t in [118,127]
        }

        float ca, cb;
        unpk2(cnt, ca, cb);
        if (acta) {
            a0 = fmaf(ca, __ldg(&w2[ha]), a0);
            a1 = fmaf(ca, __ldg(&w2[H_DIM + ha]), a1);
        }
        if (actb) {
            a0 = fmaf(cb, __ldg(&w2[hb]), a0);
            a1 = fmaf(cb, __ldg(&w2[H_DIM + hb]), a1);
        }
    }
    #pragma unroll
    for (int off = 16; off; off >>= 1) {
        a0 += __shfl_xor_sync(0xffffffffu, a0, off);
        a1 += __shfl_xor_sync(0xffffffffu, a1, off);
    }
    if (lane == 0) {
        out[b * 2 + 0] = 0.1f * a0;                  // exclusive writer for b
        out[b * 2 + 1] = 0.1f * a1;
    }
}

extern "C" void kernel_launch(void* const* d_in, const int* in_sizes, int n_in,
                              void* d_out, int out_size) {
    const float2* x  = (const float2*)d_in[0];   // [128, 8192, 2] f32
    const float2* W1 = (const float2*)d_in[1];   // [256, 2] f32
    const float*  W2 = (const float*)d_in[2];    // [2, 256] f32
    float* out = (float*)d_out;                  // [8192, 2] f32

    k1_dirmax<<<(B_TOT * NDIR) / 256, 256>>>(x);
    k2_filter<<<B_TOT, 256>>>(W1, out);
    k3_scan  <<<B_TOT / 8, 256>>>(x, W1, W2, out);
}

// round 8
// speedup vs baseline: 1.2128x; 1.2128x over previous
#include <cuda_runtime.h>
#include <cstdint>

#define T_STEPS 128
#define B_TOT   8192
#define H_DIM   256
#define BETA    0.9f
#define NDIR    16
#define SLACK   1.0205f   // sec(pi/16)=1.01959 + fp margin; strictly conservative

typedef unsigned long long u64;

// --- static device scratch (no allocation allowed) ---
__device__ int           d_cnt[B_TOT];           // survivors per batch
__device__ unsigned char d_list[B_TOT][H_DIM];   // survivor h indices per batch

__device__ const float c_cs[NDIR] = {
     1.0f,  0.92387953f,  0.70710678f,  0.38268343f,
     0.0f, -0.38268343f, -0.70710678f, -0.92387953f,
    -1.0f, -0.92387953f, -0.70710678f, -0.38268343f,
     0.0f,  0.38268343f,  0.70710678f,  0.92387953f };
__device__ const float c_sn[NDIR] = {
     0.0f,  0.38268343f,  0.70710678f,  0.92387953f,
     1.0f,  0.92387953f,  0.70710678f,  0.38268343f,
     0.0f, -0.38268343f, -0.70710678f, -0.92387953f,
    -1.0f, -0.92387953f, -0.70710678f, -0.38268343f };

// ---- packed f32x2 helpers ----
__device__ __forceinline__ u64 pk2(float lo, float hi) {
    u64 r; asm("mov.b64 %0, {%1, %2};" : "=l"(r) : "f"(lo), "f"(hi)); return r;
}
__device__ __forceinline__ void unpk2(u64 v, float& lo, float& hi) {
    asm("mov.b64 {%0, %1}, %2;" : "=f"(lo), "=f"(hi) : "l"(v));
}
__device__ __forceinline__ u64 fma2(u64 a, u64 b, u64 c) {
    u64 d; asm("fma.rn.f32x2 %0, %1, %2, %3;" : "=l"(d) : "l"(a), "l"(b), "l"(c)); return d;
}
__device__ __forceinline__ u64 mul2(u64 a, u64 b) {
    u64 d; asm("mul.rn.f32x2 %0, %1, %2;" : "=l"(d) : "l"(a), "l"(b)); return d;
}
__device__ __forceinline__ u64 add2(u64 a, u64 b) {
    u64 d; asm("add.rn.f32x2 %0, %1, %2;" : "=l"(d) : "l"(a), "l"(b)); return d;
}
__device__ __forceinline__ u64 gt1_2(u64 m) {
    u64 r;
    asm("{\n\t"
        ".reg .f32 plo, phi, rl, rh;\n\t"
        "mov.b64 {plo, phi}, %1;\n\t"
        "set.gt.f32.f32 rl, plo, 0f3F800000;\n\t"
        "set.gt.f32.f32 rh, phi, 0f3F800000;\n\t"
        "mov.b64 %0, {rl, rh};\n\t"
        "}" : "=l"(r) : "l"(m));
    return r;
}

// K12: fused directional-max + never-spikes filter + compaction, 16 b per block.
//  Phase A: stage x[:,16b] in smem (coalesced, MLP=8 per thread).
//  Phase B: thread (bl,k) runs v-recurrence from smem, D -> smem.
//  Phase C: per-warp filter over (2 b x 256 h), deterministic ballot compaction.
__global__ void __launch_bounds__(256) k12_filter(const float2* __restrict__ x2,
                                                  const float2* __restrict__ w1p,
                                                  float* __restrict__ out) {
    __shared__ float2 sx[T_STEPS][16];   // 16KB
    __shared__ float  sD[16][NDIR];      // D[bl][k]
    __shared__ float  sThr[H_DIM];       // R*SLACK per h
    __shared__ int    sSec[H_DIM];       // sector per h

    const int tid = threadIdx.x;
    const int b0  = blockIdx.x * 16;

    // per-h precompute (one thread per h)
    {
        float2 w = w1p[tid];
        float R  = sqrtf(fmaf(w.x, w.x, w.y * w.y));
        float th = atan2f(w.y, w.x);
        sSec[tid] = ((int)floorf(th * 2.5464790894703255f) + 32) & 15;  // 8/pi
        sThr[tid] = R * SLACK;
    }
    // zero this tile's outputs (32 floats)
    if (tid < 32) out[b0 * 2 + tid] = 0.f;

    // stage x: 2048 float2, 8 per thread, coalesced over bl
    #pragma unroll
    for (int i = 0; i < 8; ++i) {
        int idx = tid + i * 256;
        int t = idx >> 4, bl = idx & 15;
        sx[t][bl] = x2[(size_t)t * B_TOT + b0 + bl];
    }
    __syncthreads();

    // directional recurrence: thread = (bl = tid>>4, k = tid&15)
    {
        const int bl = tid >> 4, k = tid & 15;
        const float cs = c_cs[k], sn = c_sn[k];
        float A = 0.f, B = 0.f, D = 0.f;
        #pragma unroll 8
        for (int t = 0; t < T_STEPS; ++t) {
            float2 xv = sx[t][bl];
            A = fmaf(A, BETA, xv.x);
            B = fmaf(B, BETA, xv.y);
            D = fmaxf(D, fmaf(A, cs, B * sn));
        }
        sD[bl][k] = D;
    }
    __syncthreads();

    // filter + compaction: warp w handles bl = 2w and 2w+1
    const int wrp = tid >> 5, lane = tid & 31;
    #pragma unroll
    for (int r = 0; r < 2; ++r) {
        const int bl = wrp * 2 + r;
        const int b  = b0 + bl;
        int cnt = 0;
        #pragma unroll
        for (int c = 0; c < 8; ++c) {
            const int h = c * 32 + lane;
            const int s = sSec[h];
            float mD = fmaxf(sD[bl][s],
                             fmaxf(sD[bl][(s + 1) & 15], sD[bl][(s + 15) & 15]));
            bool pred = (sThr[h] * mD >= 1.0f);       // may spike -> survivor
            unsigned mask = __ballot_sync(0xffffffffu, pred);
            if (pred) {
                int pos = cnt + __popc(mask & ((1u << lane) - 1u));
                d_list[b][pos] = (unsigned char)h;
            }
            cnt += __popc(mask);
        }
        if (lane == 0) d_cnt[b] = cnt;
    }
}

// K3: exact reference-ordered LIF scan for survivors only.
// One warp per batch; each lane handles TWO survivors packed in f32x2
// (one pass covers 64 survivors). x staged in smem pre-duplicated
// {x0,x0,x1,x1} so one broadcast LDS.128 feeds both packed operands.
__global__ void __launch_bounds__(256) k3_scan(const float2* __restrict__ x2,
                                               const float2* __restrict__ w1p,
                                               const float*  __restrict__ w2,
                                               float* __restrict__ out) {
    const int wrp = threadIdx.x >> 5, lane = threadIdx.x & 31;
    const int b = blockIdx.x * 8 + wrp;
    const int n = d_cnt[b];
    if (n == 0) return;                              // warp-uniform; out already 0

    __shared__ __align__(16) float4 sx[8][T_STEPS];  // 16KB
    for (int t = lane; t < T_STEPS; t += 32) {
        float2 xv = x2[(size_t)t * B_TOT + b];
        sx[wrp][t] = make_float4(xv.x, xv.x, xv.y, xv.y);
    }
    __syncwarp();
    const ulonglong2* __restrict__ xs = (const ulonglong2*)&sx[wrp][0];

    const u64 BETA2 = 0x3F6666663F666666ULL;  // (0.9f, 0.9f)
    const u64 NEG12 = 0xBF800000BF800000ULL;  // (-1.0f, -1.0f)

    float a0 = 0.f, a1 = 0.f;
    for (int base = 0; base < n; base += 64) {
        const int ia = base + lane, ib = base + 32 + lane;
        const bool acta = ia < n, actb = ib < n;
        const int ha = acta ? (int)d_list[b][ia] : 0;
        const int hb = actb ? (int)d_list[b][ib] : 0;
        const float2 wa = w1p[ha], wb = w1p[hb];
        const u64 w0p = pk2(wa.x, wb.x);
        const u64 w1p_ = pk2(wa.y, wb.y);

        u64 m = 0, cnt = 0;
        #pragma unroll 4
        for (int t = 0; t < 118; ++t) {
            ulonglong2 q = xs[t];                  // q.x=(x0,x0) q.y=(x1,x1)
            u64 s = gt1_2(m);                      // reset from prev mem
            m = fma2(m, BETA2, fma2(q.x, w0p, mul2(q.y, w1p_)));
            m = fma2(s, NEG12, m);
        }
        #pragma unroll
        for (int t = 118; t < T_STEPS; ++t) {
            ulonglong2 q = xs[t];
            u64 s = gt1_2(m);
            m = fma2(m, BETA2, fma2(q.x, w0p, mul2(q.y, w1p_)));
            m = fma2(s, NEG12, m);
            cnt = add2(cnt, gt1_2(m));             // spk_t, t in [118,127]
        }

        float ca, cb;
        unpk2(cnt, ca, cb);
        if (acta) {
            a0 = fmaf(ca, __ldg(&w2[ha]), a0);
            a1 = fmaf(ca, __ldg(&w2[H_DIM + ha]), a1);
        }
        if (actb) {
            a0 = fmaf(cb, __ldg(&w2[hb]), a0);
            a1 = fmaf(cb, __ldg(&w2[H_DIM + hb]), a1);
        }
    }
    #pragma unroll
    for (int off = 16; off; off >>= 1) {
        a0 += __shfl_xor_sync(0xffffffffu, a0, off);
        a1 += __shfl_xor_sync(0xffffffffu, a1, off);
    }
    if (lane == 0) {
        out[b * 2 + 0] = 0.1f * a0;                  // exclusive writer for b
        out[b * 2 + 1] = 0.1f * a1;
    }
}

extern "C" void kernel_launch(void* const* d_in, const int* in_sizes, int n_in,
                              void* d_out, int out_size) {
    const float2* x  = (const float2*)d_in[0];   // [128, 8192, 2] f32
    const float2* W1 = (const float2*)d_in[1];   // [256, 2] f32
    const float*  W2 = (const float*)d_in[2];    // [2, 256] f32
    float* out = (float*)d_out;                  // [8192, 2] f32

    k12_filter<<<B_TOT / 16, 256>>>(x, W1, out);
    k3_scan   <<<B_TOT / 8, 256>>>(x, W1, W2, out);
}